// round 6
// baseline (speedup 1.0000x reference)
#include <cuda_runtime.h>
#include <cuda_bf16.h>
#include <cstdint>
#include <math.h>

#define H_DIM 128
#define R_DIM 6
#define D_DIM 256
#define MAX_NODES 50000

// Scratch
__device__ __align__(128) float g_agg[(size_t)MAX_NODES * H_DIM];
// Activations as bf16 hi/lo (agg split + ping-pong layers)
__device__ __align__(128) __nv_bfloat16 g_ah [(size_t)MAX_NODES * H_DIM];
__device__ __align__(128) __nv_bfloat16 g_al [(size_t)MAX_NODES * H_DIM];
__device__ __align__(128) __nv_bfloat16 g_yh0[(size_t)MAX_NODES * D_DIM];
__device__ __align__(128) __nv_bfloat16 g_yl0[(size_t)MAX_NODES * D_DIM];
__device__ __align__(128) __nv_bfloat16 g_yh1[(size_t)MAX_NODES * D_DIM];
__device__ __align__(128) __nv_bfloat16 g_yl1[(size_t)MAX_NODES * D_DIM];
// Pre-split weights: [0,32768) = W_up (256x128), then 3x Ws (256x256)
#define W_TOTAL (256*128 + 3*256*256)
__device__ __align__(128) __nv_bfloat16 g_whi[W_TOTAL];
__device__ __align__(128) __nv_bfloat16 g_wlo[W_TOTAL];

__device__ __forceinline__ uint32_t pack_bf16(float a, float b) {
    __nv_bfloat162 v(__float2bfloat16_rn(a), __float2bfloat16_rn(b));
    return *reinterpret_cast<uint32_t*>(&v);
}

// ---------------------------------------------------------------------------
// Small prep kernels
// ---------------------------------------------------------------------------
__global__ void prep_w(const float* __restrict__ W_up, const float* __restrict__ Ws,
                       __nv_bfloat16* __restrict__ whi, __nv_bfloat16* __restrict__ wlo) {
    int i = blockIdx.x * blockDim.x + threadIdx.x;
    int stride = gridDim.x * blockDim.x;
    for (; i < W_TOTAL; i += stride) {
        float v = (i < 256 * 128) ? W_up[i] : Ws[i - 256 * 128];
        __nv_bfloat16 h = __float2bfloat16_rn(v);
        whi[i] = h;
        wlo[i] = __float2bfloat16_rn(v - __bfloat162float(h));
    }
}

__global__ void zero_kernel(float4* __restrict__ p, int n4) {
    int i = blockIdx.x * blockDim.x + threadIdx.x;
    int stride = gridDim.x * blockDim.x;
    float4 z = make_float4(0.f, 0.f, 0.f, 0.f);
    for (; i < n4; i += stride) p[i] = z;
}

// fp32 -> bf16 hi/lo split (for agg)
__global__ void split_f32(const float4* __restrict__ src,
                          uint2* __restrict__ hi, uint2* __restrict__ lo, int n4) {
    int i = blockIdx.x * blockDim.x + threadIdx.x;
    int stride = gridDim.x * blockDim.x;
    for (; i < n4; i += stride) {
        float4 f = src[i];
        uint2 H, L;
        H.x = pack_bf16(f.x, f.y); H.y = pack_bf16(f.z, f.w);
        L.x = pack_bf16(f.x - __bfloat162float(__float2bfloat16_rn(f.x)),
                        f.y - __bfloat162float(__float2bfloat16_rn(f.y)));
        L.y = pack_bf16(f.z - __bfloat162float(__float2bfloat16_rn(f.z)),
                        f.w - __bfloat162float(__float2bfloat16_rn(f.w)));
        hi[i] = H; lo[i] = L;
    }
}

// ---------------------------------------------------------------------------
// Edge stage (round-5 version, 2 edges/warp-iter)
// ---------------------------------------------------------------------------
__global__ void edge_kernel(const float* __restrict__ x,
                            const float* __restrict__ rbf,
                            const int*   __restrict__ idx,
                            const float* __restrict__ Wrbf,
                            float*       __restrict__ agg,
                            int E) {
    const int lane = threadIdx.x & 31;
    const int warp = (blockIdx.x * blockDim.x + threadIdx.x) >> 5;
    const int nwarps = (gridDim.x * blockDim.x) >> 5;

    float w[4][6];
    #pragma unroll
    for (int j = 0; j < 4; ++j)
        #pragma unroll
        for (int r = 0; r < R_DIM; ++r)
            w[j][r] = __ldg(Wrbf + (lane * 4 + j) * R_DIM + r);

    for (int e0 = warp * 2; e0 < E; e0 += nwarps * 2) {
        const int e1 = e0 + 1;
        const bool has1 = e1 < E;

        const float2* rp0 = reinterpret_cast<const float2*>(rbf + (size_t)e0 * R_DIM);
        float2 a01 = __ldg(rp0 + 0), a23 = __ldg(rp0 + 1), a45 = __ldg(rp0 + 2);
        int n0 = __ldg(idx + e0);
        float4 xv0 = __ldg(reinterpret_cast<const float4*>(x + (size_t)e0 * H_DIM) + lane);

        float2 b01 = a01, b23 = a23, b45 = a45;
        int n1 = n0;
        float4 xv1 = make_float4(0.f, 0.f, 0.f, 0.f);
        if (has1) {
            const float2* rp1 = reinterpret_cast<const float2*>(rbf + (size_t)e1 * R_DIM);
            b01 = __ldg(rp1 + 0); b23 = __ldg(rp1 + 1); b45 = __ldg(rp1 + 2);
            n1 = __ldg(idx + e1);
            xv1 = __ldg(reinterpret_cast<const float4*>(x + (size_t)e1 * H_DIM) + lane);
        }

        #pragma unroll
        for (int pass = 0; pass < 2; ++pass) {
            float2 r01 = pass ? b01 : a01;
            float2 r23 = pass ? b23 : a23;
            float2 r45 = pass ? b45 : a45;
            float4 xv  = pass ? xv1 : xv0;
            int node   = pass ? n1 : n0;
            if (pass && !has1) break;

            float g0 = w[0][0]*r01.x + w[0][1]*r01.y + w[0][2]*r23.x + w[0][3]*r23.y + w[0][4]*r45.x + w[0][5]*r45.y;
            float g1 = w[1][0]*r01.x + w[1][1]*r01.y + w[1][2]*r23.x + w[1][3]*r23.y + w[1][4]*r45.x + w[1][5]*r45.y;
            float g2 = w[2][0]*r01.x + w[2][1]*r01.y + w[2][2]*r23.x + w[2][3]*r23.y + w[2][4]*r45.x + w[2][5]*r45.y;
            float g3 = w[3][0]*r01.x + w[3][1]*r01.y + w[3][2]*r23.x + w[3][3]*r23.y + w[3][4]*r45.x + w[3][5]*r45.y;

            float vx = g0 * xv.x, vy = g1 * xv.y, vz = g2 * xv.z, vw = g3 * xv.w;
            float* dst = agg + (size_t)node * H_DIM + lane * 4;
            asm volatile("red.global.add.v4.f32 [%0], {%1, %2, %3, %4};"
                         :: "l"(dst), "f"(vx), "f"(vy), "f"(vz), "f"(vw) : "memory");
        }
    }
}

// ---------------------------------------------------------------------------
// Pipelined bf16 mma GEMM (3-product split), cp.async + ldmatrix.
// CTA tile 128(m) x 128(n), grid.y = 2 covers N=256. K chunks of 32.
// SMEM: 2 stages x {Ahi, Alo, Bhi, Blo}, each 128 rows x 40 halfwords.
// ---------------------------------------------------------------------------
#define STRIDE_H 40
#define ARR_B    (128 * STRIDE_H * 2)       // 10240 bytes per array
#define STG_B    (4 * ARR_B)                // 40960 bytes per stage
#define SMEM_TOT (2 * STG_B)                // 81920 bytes

__device__ __forceinline__ void mma_bf16(float* d, const uint32_t* a, uint32_t b0, uint32_t b1) {
    asm("mma.sync.aligned.m16n8k16.row.col.f32.bf16.bf16.f32 "
        "{%0,%1,%2,%3}, {%4,%5,%6,%7}, {%8,%9}, {%0,%1,%2,%3};"
        : "+f"(d[0]), "+f"(d[1]), "+f"(d[2]), "+f"(d[3])
        : "r"(a[0]), "r"(a[1]), "r"(a[2]), "r"(a[3]), "r"(b0), "r"(b1));
}
__device__ __forceinline__ void ldsm4(uint32_t* r, uint32_t saddr) {
    asm volatile("ldmatrix.sync.aligned.m8n8.x4.shared.b16 {%0,%1,%2,%3}, [%4];"
                 : "=r"(r[0]), "=r"(r[1]), "=r"(r[2]), "=r"(r[3]) : "r"(saddr));
}
__device__ __forceinline__ void cp16(uint32_t dst, const void* src, bool valid) {
    asm volatile("cp.async.ca.shared.global [%0], [%1], 16, %2;"
                 :: "r"(dst), "l"(src), "r"(valid ? 16 : 0) : "memory");
}

template<int K_TOTAL, bool BIAS, bool SILU, bool PROJ>
__global__ void __launch_bounds__(256)
gemm_cp(const __nv_bfloat16* __restrict__ Ahi, const __nv_bfloat16* __restrict__ Alo,
        const __nv_bfloat16* __restrict__ Bhi, const __nv_bfloat16* __restrict__ Blo,
        const float* __restrict__ bias, const float* __restrict__ wout,
        __nv_bfloat16* __restrict__ Yhi, __nv_bfloat16* __restrict__ Ylo,
        float* __restrict__ Yproj, int M) {
    extern __shared__ __align__(16) char smem[];
    constexpr int NC = K_TOTAL / 32;
    const uint32_t sbase = (uint32_t)__cvta_generic_to_shared(smem);

    const int tid  = threadIdx.x;
    const int wid  = tid >> 5, lane = tid & 31;
    const int g    = lane >> 2, t = lane & 3;
    const int m0   = blockIdx.x * 128;
    const int n0   = blockIdx.y * 128;
    const int wm   = (wid & 3) * 32;
    const int wn   = (wid >> 2) * 64;

    float acc[2][8][4];
    #pragma unroll
    for (int i = 0; i < 2; ++i)
        #pragma unroll
        for (int j = 0; j < 8; ++j)
            #pragma unroll
            for (int q = 0; q < 4; ++q) acc[i][j][q] = 0.f;

    // fill addressing
    const int fr = tid & 127, fh = tid >> 7;
    const bool a_valid = (m0 + fr) < M;
    const uint32_t fill_d = sbase + (uint32_t)(fr * STRIDE_H + fh * 16) * 2;

    // fragment addressing (bytes)
    const uint32_t a_off = (uint32_t)((wm + (lane & 15)) * STRIDE_H + ((lane & 16) ? 8 : 0)) * 2;
    const uint32_t b_off = (uint32_t)((wn + (lane & 7) + ((lane & 16) ? 8 : 0)) * STRIDE_H
                                      + ((lane & 8) ? 8 : 0)) * 2;

    auto fill = [&](int c, int s) {
        size_t ga = (size_t)(m0 + fr) * K_TOTAL + c * 32 + fh * 16;
        size_t gb = (size_t)(n0 + fr) * K_TOTAL + c * 32 + fh * 16;
        uint32_t d = fill_d + s * STG_B;
        #pragma unroll
        for (int q = 0; q < 2; ++q) {
            cp16(d + 0 * ARR_B + q * 16, Ahi + ga + q * 8, a_valid);
            cp16(d + 1 * ARR_B + q * 16, Alo + ga + q * 8, a_valid);
            cp16(d + 2 * ARR_B + q * 16, Bhi + gb + q * 8, true);
            cp16(d + 3 * ARR_B + q * 16, Blo + gb + q * 8, true);
        }
        asm volatile("cp.async.commit_group;" ::: "memory");
    };

    auto compute = [&](int s) {
        const uint32_t A0 = sbase + s * STG_B + a_off;
        const uint32_t A1 = A0 + ARR_B;
        const uint32_t B0 = sbase + s * STG_B + 2 * ARR_B + b_off;
        const uint32_t B1 = B0 + ARR_B;
        #pragma unroll
        for (int ks = 0; ks < 2; ++ks) {
            const uint32_t ko = ks * 32;
            uint32_t ah[2][4], al[2][4];
            ldsm4(ah[0], A0 + ko);        ldsm4(ah[1], A0 + 1280 + ko);
            ldsm4(al[0], A1 + ko);        ldsm4(al[1], A1 + 1280 + ko);
            #pragma unroll
            for (int p = 0; p < 4; ++p) {
                uint32_t bh[4], bl[4];
                ldsm4(bh, B0 + p * 1280 + ko);
                ldsm4(bl, B1 + p * 1280 + ko);
                #pragma unroll
                for (int j2 = 0; j2 < 2; ++j2) {
                    const int j = p * 2 + j2;
                    #pragma unroll
                    for (int i = 0; i < 2; ++i) {
                        mma_bf16(acc[i][j], ah[i], bh[j2 * 2], bh[j2 * 2 + 1]);
                        mma_bf16(acc[i][j], ah[i], bl[j2 * 2], bl[j2 * 2 + 1]);
                        mma_bf16(acc[i][j], al[i], bh[j2 * 2], bh[j2 * 2 + 1]);
                    }
                }
            }
        }
    };

    // pipeline
    fill(0, 0);
    asm volatile("cp.async.wait_group 0;" ::: "memory");
    __syncthreads();
    for (int c = 0; c < NC; ++c) {
        if (c + 1 < NC) fill(c + 1, (c + 1) & 1);
        compute(c & 1);
        if (c + 1 < NC)
            asm volatile("cp.async.wait_group 0;" ::: "memory");
        __syncthreads();
    }

    // ---- epilogue ----
    if (PROJ) {
        float s[4] = {0.f, 0.f, 0.f, 0.f};
        #pragma unroll
        for (int i = 0; i < 2; ++i)
            #pragma unroll
            for (int j = 0; j < 8; ++j) {
                int col = n0 + wn + j * 8 + t * 2;
                float w0 = __ldg(wout + col), w1 = __ldg(wout + col + 1);
                float b0 = BIAS ? __ldg(bias + col) : 0.f;
                float b1 = BIAS ? __ldg(bias + col + 1) : 0.f;
                float v0 = acc[i][j][0] + b0, v1 = acc[i][j][1] + b1;
                float v2 = acc[i][j][2] + b0, v3 = acc[i][j][3] + b1;
                if (SILU) {
                    v0 = v0 / (1.f + __expf(-v0)); v1 = v1 / (1.f + __expf(-v1));
                    v2 = v2 / (1.f + __expf(-v2)); v3 = v3 / (1.f + __expf(-v3));
                }
                s[i * 2 + 0] += v0 * w0 + v1 * w1;
                s[i * 2 + 1] += v2 * w0 + v3 * w1;
            }
        #pragma unroll
        for (int q = 0; q < 4; ++q) {
            s[q] += __shfl_xor_sync(0xffffffffu, s[q], 1);
            s[q] += __shfl_xor_sync(0xffffffffu, s[q], 2);
        }
        if (t == 0) {
            #pragma unroll
            for (int i = 0; i < 2; ++i) {
                int r0 = m0 + wm + i * 16 + g;
                if (r0 < M)
                    asm volatile("red.global.add.f32 [%0], %1;" :: "l"(Yproj + r0), "f"(s[i*2]) : "memory");
                if (r0 + 8 < M)
                    asm volatile("red.global.add.f32 [%0], %1;" :: "l"(Yproj + r0 + 8), "f"(s[i*2+1]) : "memory");
            }
        }
    } else {
        #pragma unroll
        for (int i = 0; i < 2; ++i) {
            int r0 = m0 + wm + i * 16 + g;
            #pragma unroll
            for (int j = 0; j < 8; ++j) {
                int col = n0 + wn + j * 8 + t * 2;
                float b0 = BIAS ? __ldg(bias + col) : 0.f;
                float b1 = BIAS ? __ldg(bias + col + 1) : 0.f;
                float v0 = acc[i][j][0] + b0, v1 = acc[i][j][1] + b1;
                float v2 = acc[i][j][2] + b0, v3 = acc[i][j][3] + b1;
                if (SILU) {
                    v0 = v0 / (1.f + __expf(-v0)); v1 = v1 / (1.f + __expf(-v1));
                    v2 = v2 / (1.f + __expf(-v2)); v3 = v3 / (1.f + __expf(-v3));
                }
                uint32_t h01 = pack_bf16(v0, v1);
                uint32_t h23 = pack_bf16(v2, v3);
                uint32_t L01 = pack_bf16(v0 - __bfloat162float(__float2bfloat16_rn(v0)),
                                         v1 - __bfloat162float(__float2bfloat16_rn(v1)));
                uint32_t L23 = pack_bf16(v2 - __bfloat162float(__float2bfloat16_rn(v2)),
                                         v3 - __bfloat162float(__float2bfloat16_rn(v3)));
                if (r0 < M) {
                    *reinterpret_cast<uint32_t*>(Yhi + (size_t)r0 * D_DIM + col) = h01;
                    *reinterpret_cast<uint32_t*>(Ylo + (size_t)r0 * D_DIM + col) = L01;
                }
                if (r0 + 8 < M) {
                    *reinterpret_cast<uint32_t*>(Yhi + (size_t)(r0 + 8) * D_DIM + col) = h23;
                    *reinterpret_cast<uint32_t*>(Ylo + (size_t)(r0 + 8) * D_DIM + col) = L23;
                }
            }
        }
    }
}

// ---------------------------------------------------------------------------
// Launch
// ---------------------------------------------------------------------------
extern "C" void kernel_launch(void* const* d_in, const int* in_sizes, int n_in,
                              void* d_out, int out_size) {
    const float* x     = (const float*)d_in[0];
    const float* rbf   = (const float*)d_in[1];
    const int*   idx   = (const int*)  d_in[2];
    const float* W_rbf = (const float*)d_in[3];
    const float* W_up  = (const float*)d_in[4];
    const float* Ws    = (const float*)d_in[5];
    const float* bs    = (const float*)d_in[6];
    const float* W_out = (const float*)d_in[7];
    float* out = (float*)d_out;

    const int E = in_sizes[2];
    const int M = out_size;

    float* agg;
    __nv_bfloat16 *whi, *wlo, *ah, *al, *yh0, *yl0, *yh1, *yl1;
    cudaGetSymbolAddress((void**)&agg, g_agg);
    cudaGetSymbolAddress((void**)&whi, g_whi);
    cudaGetSymbolAddress((void**)&wlo, g_wlo);
    cudaGetSymbolAddress((void**)&ah,  g_ah);
    cudaGetSymbolAddress((void**)&al,  g_al);
    cudaGetSymbolAddress((void**)&yh0, g_yh0);
    cudaGetSymbolAddress((void**)&yl0, g_yl0);
    cudaGetSymbolAddress((void**)&yh1, g_yh1);
    cudaGetSymbolAddress((void**)&yl1, g_yl1);

    cudaFuncSetAttribute(gemm_cp<128, false, false, false>, cudaFuncAttributeMaxDynamicSharedMemorySize, SMEM_TOT);
    cudaFuncSetAttribute(gemm_cp<256, true,  true,  false>, cudaFuncAttributeMaxDynamicSharedMemorySize, SMEM_TOT);
    cudaFuncSetAttribute(gemm_cp<256, true,  true,  true >, cudaFuncAttributeMaxDynamicSharedMemorySize, SMEM_TOT);

    prep_w<<<224, 256>>>(W_up, Ws, whi, wlo);
    zero_kernel<<<1024, 256>>>((float4*)agg, M * H_DIM / 4);
    zero_kernel<<<128, 256>>>((float4*)out, M / 4);

    edge_kernel<<<1184, 256>>>(x, rbf, idx, W_rbf, agg, E);

    // split agg into bf16 hi/lo
    split_f32<<<1024, 256>>>((const float4*)agg, (uint2*)ah, (uint2*)al, M * H_DIM / 4);

    const int tiles = (M + 127) / 128;
    dim3 grid(tiles, 2);
    const __nv_bfloat16* whi_l = whi + 256 * 128;
    const __nv_bfloat16* wlo_l = wlo + 256 * 128;

    // up-projection: yh0/yl0 = agg @ W_up^T
    gemm_cp<128, false, false, false><<<grid, 256, SMEM_TOT>>>(
        ah, al, whi, wlo, nullptr, nullptr, yh0, yl0, nullptr, M);
    // layer 0: yh1/yl1 = silu(y0 @ W0^T + b0)
    gemm_cp<256, true, true, false><<<grid, 256, SMEM_TOT>>>(
        yh0, yl0, whi_l + 0*65536, wlo_l + 0*65536, bs + 0*D_DIM, nullptr, yh1, yl1, nullptr, M);
    // layer 1: yh0/yl0 = silu(y1 @ W1^T + b1)
    gemm_cp<256, true, true, false><<<grid, 256, SMEM_TOT>>>(
        yh1, yl1, whi_l + 1*65536, wlo_l + 1*65536, bs + 1*D_DIM, nullptr, yh0, yl0, nullptr, M);
    // layer 2 + fused projection into out
    gemm_cp<256, true, true, true><<<grid, 256, SMEM_TOT>>>(
        yh0, yl0, whi_l + 2*65536, wlo_l + 2*65536, bs + 2*D_DIM, W_out, nullptr, nullptr, out, M);
}

// round 8
// speedup vs baseline: 1.2123x; 1.2123x over previous
#include <cuda_runtime.h>
#include <cuda_bf16.h>
#include <cstdint>
#include <math.h>

#define H_DIM 128
#define R_DIM 6
#define D_DIM 256
#define MAX_NODES 50000

// Scratch
__device__ __align__(128) float g_agg[(size_t)MAX_NODES * H_DIM];   // 25.6 MB
__device__ __align__(128) float g_y0 [(size_t)MAX_NODES * D_DIM];   // 51.2 MB
__device__ __align__(128) float g_y1 [(size_t)MAX_NODES * D_DIM];   // 51.2 MB
// Pre-split weights: [0,32768) = W_up (256x128), then 3x Ws (256x256)
#define W_TOTAL (256*128 + 3*256*256)
__device__ __align__(128) __nv_bfloat16 g_whi[W_TOTAL];
__device__ __align__(128) __nv_bfloat16 g_wlo[W_TOTAL];

__device__ __forceinline__ uint32_t pack_bf16(float a, float b) {
    __nv_bfloat162 v(__float2bfloat16_rn(a), __float2bfloat16_rn(b));
    return *reinterpret_cast<uint32_t*>(&v);
}

// ---------------------------------------------------------------------------
// Prep kernels
// ---------------------------------------------------------------------------
__global__ void prep_w(const float* __restrict__ W_up, const float* __restrict__ Ws,
                       __nv_bfloat16* __restrict__ whi, __nv_bfloat16* __restrict__ wlo) {
    int i = blockIdx.x * blockDim.x + threadIdx.x;
    int stride = gridDim.x * blockDim.x;
    for (; i < W_TOTAL; i += stride) {
        float v = (i < 256 * 128) ? W_up[i] : Ws[i - 256 * 128];
        __nv_bfloat16 h = __float2bfloat16_rn(v);
        whi[i] = h;
        wlo[i] = __float2bfloat16_rn(v - __bfloat162float(h));
    }
}

__global__ void zero_kernel(float4* __restrict__ p, int n4) {
    int i = blockIdx.x * blockDim.x + threadIdx.x;
    int stride = gridDim.x * blockDim.x;
    float4 z = make_float4(0.f, 0.f, 0.f, 0.f);
    for (; i < n4; i += stride) p[i] = z;
}

// ---------------------------------------------------------------------------
// Edge stage v3: half-edge per warp (lane owns 2 channels) for low regs /
// high occupancy. task = global warp id; e = task>>1; h = task&1 (constant
// per warp since total warp count is even); channels [h*64, h*64+64).
// ---------------------------------------------------------------------------
__global__ void __launch_bounds__(256)
edge_kernel(const float* __restrict__ x,
            const float* __restrict__ rbf,
            const int*   __restrict__ idx,
            const float* __restrict__ Wrbf,
            float*       __restrict__ agg,
            int E) {
    const int lane  = threadIdx.x & 31;
    const int gwarp = (blockIdx.x * blockDim.x + threadIdx.x) >> 5;
    const int nwarps = (gridDim.x * blockDim.x) >> 5;   // even
    const int h  = gwarp & 1;
    const int ch = h * 64 + lane * 2;

    float w0[6], w1[6];
    #pragma unroll
    for (int r = 0; r < R_DIM; ++r) {
        w0[r] = __ldg(Wrbf + (ch + 0) * R_DIM + r);
        w1[r] = __ldg(Wrbf + (ch + 1) * R_DIM + r);
    }

    for (int task = gwarp; (task >> 1) < E; task += nwarps) {
        const int e = task >> 1;
        const float2* rp = reinterpret_cast<const float2*>(rbf + (size_t)e * R_DIM);
        float2 r01 = __ldg(rp + 0);
        float2 r23 = __ldg(rp + 1);
        float2 r45 = __ldg(rp + 2);
        int node = __ldg(idx + e);
        float2 xv = __ldg(reinterpret_cast<const float2*>(x + (size_t)e * H_DIM + ch));

        float g0 = w0[0]*r01.x + w0[1]*r01.y + w0[2]*r23.x + w0[3]*r23.y + w0[4]*r45.x + w0[5]*r45.y;
        float g1 = w1[0]*r01.x + w1[1]*r01.y + w1[2]*r23.x + w1[3]*r23.y + w1[4]*r45.x + w1[5]*r45.y;

        float v0 = g0 * xv.x, v1 = g1 * xv.y;
        float* dst = agg + (size_t)node * H_DIM + ch;
        asm volatile("red.global.add.v2.f32 [%0], {%1, %2};"
                     :: "l"(dst), "f"(v0), "f"(v1) : "memory");
    }
}

// ---------------------------------------------------------------------------
// Round-4 GEMM (proven): bf16 mma.sync, 3-product split.
// CTA tile 128(m) x 128(n), 8 warps of 32x64, K chunks of 32.
// A is fp32, converted to bf16 hi/lo during SMEM fill.
// ---------------------------------------------------------------------------
#define STRIDE_H 40   // halfwords per SMEM row (32 data + 8 pad)

__device__ __forceinline__ void mma_bf16(float* d, const uint32_t* a, uint32_t b0, uint32_t b1) {
    asm("mma.sync.aligned.m16n8k16.row.col.f32.bf16.bf16.f32 "
        "{%0,%1,%2,%3}, {%4,%5,%6,%7}, {%8,%9}, {%0,%1,%2,%3};"
        : "+f"(d[0]), "+f"(d[1]), "+f"(d[2]), "+f"(d[3])
        : "r"(a[0]), "r"(a[1]), "r"(a[2]), "r"(a[3]), "r"(b0), "r"(b1));
}

template<int K_TOTAL, bool BIAS, bool SILU, bool PROJ>
__global__ void __launch_bounds__(256, 2)
gemm_mma(const float* __restrict__ A,
         const __nv_bfloat16* __restrict__ Bhi,
         const __nv_bfloat16* __restrict__ Blo,
         const float* __restrict__ bias,
         const float* __restrict__ wout,
         float* __restrict__ Y,
         int M) {
    __shared__ __align__(16) uint16_t sAhi[128 * STRIDE_H];
    __shared__ __align__(16) uint16_t sAlo[128 * STRIDE_H];
    __shared__ __align__(16) uint16_t sBhi[128 * STRIDE_H];
    __shared__ __align__(16) uint16_t sBlo[128 * STRIDE_H];

    const int tid  = threadIdx.x;
    const int wid  = tid >> 5, lane = tid & 31;
    const int g    = lane >> 2, t = lane & 3;
    const int m0   = blockIdx.x * 128;
    const int n0   = blockIdx.y * 128;
    const int wm   = (wid & 3) * 32;
    const int wn   = (wid >> 2) * 64;

    float acc[2][8][4];
    #pragma unroll
    for (int i = 0; i < 2; ++i)
        #pragma unroll
        for (int j = 0; j < 8; ++j)
            #pragma unroll
            for (int q = 0; q < 4; ++q) acc[i][j][q] = 0.f;

    const uint32_t* A32hi = reinterpret_cast<const uint32_t*>(sAhi);
    const uint32_t* A32lo = reinterpret_cast<const uint32_t*>(sAlo);
    const uint32_t* B32hi = reinterpret_cast<const uint32_t*>(sBhi);
    const uint32_t* B32lo = reinterpret_cast<const uint32_t*>(sBlo);

    const int fr = tid >> 1;
    const int fh = tid & 1;
    const bool a_valid = (m0 + fr) < M;

    for (int c = 0; c < K_TOTAL / 32; ++c) {
        // ---- fill A (fp32 -> bf16 hi/lo) ----
        {
            const float* ap = A + (size_t)(m0 + fr) * K_TOTAL + c * 32 + fh * 16;
            #pragma unroll
            for (int q4 = 0; q4 < 2; ++q4) {
                float4 f0 = make_float4(0.f,0.f,0.f,0.f), f1 = f0;
                if (a_valid) {
                    f0 = *reinterpret_cast<const float4*>(ap + q4 * 8);
                    f1 = *reinterpret_cast<const float4*>(ap + q4 * 8 + 4);
                }
                uint4 Hv, Lv;
                Hv.x = pack_bf16(f0.x, f0.y); Hv.y = pack_bf16(f0.z, f0.w);
                Hv.z = pack_bf16(f1.x, f1.y); Hv.w = pack_bf16(f1.z, f1.w);
                float e0 = f0.x - __bfloat162float(__float2bfloat16_rn(f0.x));
                float e1 = f0.y - __bfloat162float(__float2bfloat16_rn(f0.y));
                float e2 = f0.z - __bfloat162float(__float2bfloat16_rn(f0.z));
                float e3 = f0.w - __bfloat162float(__float2bfloat16_rn(f0.w));
                float e4 = f1.x - __bfloat162float(__float2bfloat16_rn(f1.x));
                float e5 = f1.y - __bfloat162float(__float2bfloat16_rn(f1.y));
                float e6 = f1.z - __bfloat162float(__float2bfloat16_rn(f1.z));
                float e7 = f1.w - __bfloat162float(__float2bfloat16_rn(f1.w));
                Lv.x = pack_bf16(e0, e1); Lv.y = pack_bf16(e2, e3);
                Lv.z = pack_bf16(e4, e5); Lv.w = pack_bf16(e6, e7);
                int hw = fr * STRIDE_H + fh * 16 + q4 * 8;
                *reinterpret_cast<uint4*>(sAhi + hw) = Hv;
                *reinterpret_cast<uint4*>(sAlo + hw) = Lv;
            }
        }
        // ---- fill B ----
        {
            const size_t boff = (size_t)(n0 + fr) * K_TOTAL + c * 32 + fh * 16;
            const uint4* bh = reinterpret_cast<const uint4*>(Bhi + boff);
            const uint4* bl = reinterpret_cast<const uint4*>(Blo + boff);
            int hw = fr * STRIDE_H + fh * 16;
            *reinterpret_cast<uint4*>(sBhi + hw)     = bh[0];
            *reinterpret_cast<uint4*>(sBhi + hw + 8) = bh[1];
            *reinterpret_cast<uint4*>(sBlo + hw)     = bl[0];
            *reinterpret_cast<uint4*>(sBlo + hw + 8) = bl[1];
        }
        __syncthreads();

        // ---- compute ----
        #pragma unroll
        for (int ks = 0; ks < 2; ++ks) {
            const int kw = ks * 8;
            uint32_t ahi[2][4], alo[2][4];
            #pragma unroll
            for (int i = 0; i < 2; ++i) {
                int r0 = (wm + i * 16 + g) * (STRIDE_H / 2) + kw + t;
                ahi[i][0] = A32hi[r0];        ahi[i][1] = A32hi[r0 + 160];
                ahi[i][2] = A32hi[r0 + 4];    ahi[i][3] = A32hi[r0 + 164];
                alo[i][0] = A32lo[r0];        alo[i][1] = A32lo[r0 + 160];
                alo[i][2] = A32lo[r0 + 4];    alo[i][3] = A32lo[r0 + 164];
            }
            #pragma unroll
            for (int j = 0; j < 8; ++j) {
                int nb = (wn + j * 8 + g) * (STRIDE_H / 2) + kw + t;
                uint32_t bh0 = B32hi[nb], bh1 = B32hi[nb + 4];
                uint32_t bl0 = B32lo[nb], bl1 = B32lo[nb + 4];
                #pragma unroll
                for (int i = 0; i < 2; ++i) {
                    mma_bf16(acc[i][j], ahi[i], bh0, bh1);
                    mma_bf16(acc[i][j], ahi[i], bl0, bl1);
                    mma_bf16(acc[i][j], alo[i], bh0, bh1);
                }
            }
        }
        __syncthreads();
    }

    // ---- epilogue ----
    if (PROJ) {
        float s[4] = {0.f, 0.f, 0.f, 0.f};
        #pragma unroll
        for (int i = 0; i < 2; ++i)
            #pragma unroll
            for (int j = 0; j < 8; ++j) {
                int col = n0 + wn + j * 8 + t * 2;
                float w0 = __ldg(wout + col), w1 = __ldg(wout + col + 1);
                float b0 = BIAS ? __ldg(bias + col) : 0.f;
                float b1 = BIAS ? __ldg(bias + col + 1) : 0.f;
                float v0 = acc[i][j][0] + b0, v1 = acc[i][j][1] + b1;
                float v2 = acc[i][j][2] + b0, v3 = acc[i][j][3] + b1;
                if (SILU) {
                    v0 = v0 / (1.f + __expf(-v0)); v1 = v1 / (1.f + __expf(-v1));
                    v2 = v2 / (1.f + __expf(-v2)); v3 = v3 / (1.f + __expf(-v3));
                }
                s[i * 2 + 0] += v0 * w0 + v1 * w1;
                s[i * 2 + 1] += v2 * w0 + v3 * w1;
            }
        #pragma unroll
        for (int q = 0; q < 4; ++q) {
            s[q] += __shfl_xor_sync(0xffffffffu, s[q], 1);
            s[q] += __shfl_xor_sync(0xffffffffu, s[q], 2);
        }
        if (t == 0) {
            #pragma unroll
            for (int i = 0; i < 2; ++i) {
                int r0 = m0 + wm + i * 16 + g;
                if (r0 < M)
                    asm volatile("red.global.add.f32 [%0], %1;" :: "l"(Y + r0), "f"(s[i*2]) : "memory");
                if (r0 + 8 < M)
                    asm volatile("red.global.add.f32 [%0], %1;" :: "l"(Y + r0 + 8), "f"(s[i*2+1]) : "memory");
            }
        }
    } else {
        #pragma unroll
        for (int i = 0; i < 2; ++i) {
            int r0 = m0 + wm + i * 16 + g;
            #pragma unroll
            for (int j = 0; j < 8; ++j) {
                int col = n0 + wn + j * 8 + t * 2;
                float b0 = BIAS ? __ldg(bias + col) : 0.f;
                float b1 = BIAS ? __ldg(bias + col + 1) : 0.f;
                float v0 = acc[i][j][0] + b0, v1 = acc[i][j][1] + b1;
                float v2 = acc[i][j][2] + b0, v3 = acc[i][j][3] + b1;
                if (SILU) {
                    v0 = v0 / (1.f + __expf(-v0)); v1 = v1 / (1.f + __expf(-v1));
                    v2 = v2 / (1.f + __expf(-v2)); v3 = v3 / (1.f + __expf(-v3));
                }
                if (r0 < M)
                    *reinterpret_cast<float2*>(Y + (size_t)r0 * D_DIM + col) = make_float2(v0, v1);
                if (r0 + 8 < M)
                    *reinterpret_cast<float2*>(Y + (size_t)(r0 + 8) * D_DIM + col) = make_float2(v2, v3);
            }
        }
    }
}

// ---------------------------------------------------------------------------
// Launch
// Inputs: 0:x[E,128] 1:rbf[E,6] 2:i[E] 3:W_rbf[128,6] 4:W_up[256,128]
//         5:Ws[3,256,256] 6:bs[3,256] 7:W_out[1,256] (8:num_nodes)
// ---------------------------------------------------------------------------
extern "C" void kernel_launch(void* const* d_in, const int* in_sizes, int n_in,
                              void* d_out, int out_size) {
    const float* x     = (const float*)d_in[0];
    const float* rbf   = (const float*)d_in[1];
    const int*   idx   = (const int*)  d_in[2];
    const float* W_rbf = (const float*)d_in[3];
    const float* W_up  = (const float*)d_in[4];
    const float* Ws    = (const float*)d_in[5];
    const float* bs    = (const float*)d_in[6];
    const float* W_out = (const float*)d_in[7];
    float* out = (float*)d_out;

    const int E = in_sizes[2];
    const int M = out_size;

    float *agg, *y0, *y1;
    __nv_bfloat16 *whi, *wlo;
    cudaGetSymbolAddress((void**)&agg, g_agg);
    cudaGetSymbolAddress((void**)&y0,  g_y0);
    cudaGetSymbolAddress((void**)&y1,  g_y1);
    cudaGetSymbolAddress((void**)&whi, g_whi);
    cudaGetSymbolAddress((void**)&wlo, g_wlo);

    prep_w<<<224, 256>>>(W_up, Ws, whi, wlo);
    zero_kernel<<<1024, 256>>>((float4*)agg, M * H_DIM / 4);
    zero_kernel<<<128, 256>>>((float4*)out, M / 4);

    edge_kernel<<<1184, 256>>>(x, rbf, idx, W_rbf, agg, E);

    const int tiles = (M + 127) / 128;
    dim3 grid(tiles, 2);
    const __nv_bfloat16* whi_l = whi + 256 * 128;
    const __nv_bfloat16* wlo_l = wlo + 256 * 128;

    // up-projection: y0 = agg @ W_up^T
    gemm_mma<128, false, false, false><<<grid, 256>>>(agg, whi, wlo, nullptr, nullptr, y0, M);
    // layer 0: y1 = silu(y0 @ W0^T + b0)
    gemm_mma<256, true, true, false><<<grid, 256>>>(y0, whi_l + 0*65536, wlo_l + 0*65536, bs + 0*D_DIM, nullptr, y1, M);
    // layer 1: y0 = silu(y1 @ W1^T + b1)
    gemm_mma<256, true, true, false><<<grid, 256>>>(y1, whi_l + 1*65536, wlo_l + 1*65536, bs + 1*D_DIM, nullptr, y0, M);
    // layer 2 + fused projection into out (wout passed as bias slot order: bias, wout)
    gemm_mma<256, true, true, true ><<<grid, 256>>>(y0, whi_l + 2*65536, wlo_l + 2*65536, bs + 2*D_DIM, W_out, out, M);
}

// round 9
// speedup vs baseline: 1.2763x; 1.0528x over previous
#include <cuda_runtime.h>
#include <cuda_bf16.h>
#include <cstdint>
#include <math.h>

#define H_DIM 128
#define R_DIM 6
#define D_DIM 256
#define MAX_NODES 50000

// Scratch
__device__ __align__(128) float g_agg[(size_t)MAX_NODES * H_DIM];   // 25.6 MB
__device__ __align__(128) float g_y0 [(size_t)MAX_NODES * D_DIM];   // 51.2 MB
__device__ __align__(128) float g_y1 [(size_t)MAX_NODES * D_DIM];   // 51.2 MB
// Pre-split weights: [0,32768) = W_up (256x128), then 3x Ws (256x256)
#define W_TOTAL (256*128 + 3*256*256)
__device__ __align__(128) __nv_bfloat16 g_whi[W_TOTAL];
__device__ __align__(128) __nv_bfloat16 g_wlo[W_TOTAL];

__device__ __forceinline__ uint32_t pack_bf16(float a, float b) {
    __nv_bfloat162 v(__float2bfloat16_rn(a), __float2bfloat16_rn(b));
    return *reinterpret_cast<uint32_t*>(&v);
}

// ---------------------------------------------------------------------------
// Prep kernels
// ---------------------------------------------------------------------------
__global__ void prep_w(const float* __restrict__ W_up, const float* __restrict__ Ws,
                       __nv_bfloat16* __restrict__ whi, __nv_bfloat16* __restrict__ wlo) {
    int i = blockIdx.x * blockDim.x + threadIdx.x;
    int stride = gridDim.x * blockDim.x;
    for (; i < W_TOTAL; i += stride) {
        float v = (i < 256 * 128) ? W_up[i] : Ws[i - 256 * 128];
        __nv_bfloat16 h = __float2bfloat16_rn(v);
        whi[i] = h;
        wlo[i] = __float2bfloat16_rn(v - __bfloat162float(h));
    }
}

__global__ void zero_kernel(float4* __restrict__ p, int n4) {
    int i = blockIdx.x * blockDim.x + threadIdx.x;
    int stride = gridDim.x * blockDim.x;
    float4 z = make_float4(0.f, 0.f, 0.f, 0.f);
    for (; i < n4; i += stride) p[i] = z;
}

// ---------------------------------------------------------------------------
// Edge stage v4: 4-edge batch per warp, 4 channels/lane, red.v4.
// All global loads for the batch issued before any compute -> high MLP.
// ---------------------------------------------------------------------------
__global__ void __launch_bounds__(256, 3)
edge_kernel(const float* __restrict__ x,
            const float* __restrict__ rbf,
            const int*   __restrict__ idx,
            const float* __restrict__ Wrbf,
            float*       __restrict__ agg,
            int E) {
    const int lane = threadIdx.x & 31;
    const int warp = (blockIdx.x * blockDim.x + threadIdx.x) >> 5;
    const int nwarps = (gridDim.x * blockDim.x) >> 5;

    float w[4][6];
    #pragma unroll
    for (int j = 0; j < 4; ++j)
        #pragma unroll
        for (int r = 0; r < R_DIM; ++r)
            w[j][r] = __ldg(Wrbf + (lane * 4 + j) * R_DIM + r);

    for (int base = warp * 4; base < E; base += nwarps * 4) {
        float2 rb[4][3];
        int    nd[4];
        float4 xv[4];
        // ---- batched loads (independent, back-to-back) ----
        #pragma unroll
        for (int k = 0; k < 4; ++k) {
            int e = base + k;
            bool valid = e < E;
            const float2* rp = reinterpret_cast<const float2*>(rbf + (size_t)(valid ? e : 0) * R_DIM);
            rb[k][0] = __ldg(rp + 0);
            rb[k][1] = __ldg(rp + 1);
            rb[k][2] = __ldg(rp + 2);
            nd[k] = valid ? __ldg(idx + e) : -1;
            xv[k] = __ldg(reinterpret_cast<const float4*>(x + (size_t)(valid ? e : 0) * H_DIM) + lane);
        }
        // ---- compute + scatter ----
        #pragma unroll
        for (int k = 0; k < 4; ++k) {
            if (nd[k] < 0) break;
            float2 r01 = rb[k][0], r23 = rb[k][1], r45 = rb[k][2];
            float g0 = w[0][0]*r01.x + w[0][1]*r01.y + w[0][2]*r23.x + w[0][3]*r23.y + w[0][4]*r45.x + w[0][5]*r45.y;
            float g1 = w[1][0]*r01.x + w[1][1]*r01.y + w[1][2]*r23.x + w[1][3]*r23.y + w[1][4]*r45.x + w[1][5]*r45.y;
            float g2 = w[2][0]*r01.x + w[2][1]*r01.y + w[2][2]*r23.x + w[2][3]*r23.y + w[2][4]*r45.x + w[2][5]*r45.y;
            float g3 = w[3][0]*r01.x + w[3][1]*r01.y + w[3][2]*r23.x + w[3][3]*r23.y + w[3][4]*r45.x + w[3][5]*r45.y;
            float vx = g0 * xv[k].x, vy = g1 * xv[k].y, vz = g2 * xv[k].z, vw = g3 * xv[k].w;
            float* dst = agg + (size_t)nd[k] * H_DIM + lane * 4;
            asm volatile("red.global.add.v4.f32 [%0], {%1, %2, %3, %4};"
                         :: "l"(dst), "f"(vx), "f"(vy), "f"(vz), "f"(vw) : "memory");
        }
    }
}

// ---------------------------------------------------------------------------
// Round-4 GEMM (proven): bf16 mma.sync, 3-product split.
// CTA tile 128(m) x 128(n), 8 warps of 32x64, K chunks of 32.
// A is fp32, converted to bf16 hi/lo during SMEM fill.
// ---------------------------------------------------------------------------
#define STRIDE_H 40   // halfwords per SMEM row (32 data + 8 pad)

__device__ __forceinline__ void mma_bf16(float* d, const uint32_t* a, uint32_t b0, uint32_t b1) {
    asm("mma.sync.aligned.m16n8k16.row.col.f32.bf16.bf16.f32 "
        "{%0,%1,%2,%3}, {%4,%5,%6,%7}, {%8,%9}, {%0,%1,%2,%3};"
        : "+f"(d[0]), "+f"(d[1]), "+f"(d[2]), "+f"(d[3])
        : "r"(a[0]), "r"(a[1]), "r"(a[2]), "r"(a[3]), "r"(b0), "r"(b1));
}

template<int K_TOTAL, bool BIAS, bool SILU, bool PROJ>
__global__ void __launch_bounds__(256, 2)
gemm_mma(const float* __restrict__ A,
         const __nv_bfloat16* __restrict__ Bhi,
         const __nv_bfloat16* __restrict__ Blo,
         const float* __restrict__ bias,
         const float* __restrict__ wout,
         float* __restrict__ Y,
         int M) {
    __shared__ __align__(16) uint16_t sAhi[128 * STRIDE_H];
    __shared__ __align__(16) uint16_t sAlo[128 * STRIDE_H];
    __shared__ __align__(16) uint16_t sBhi[128 * STRIDE_H];
    __shared__ __align__(16) uint16_t sBlo[128 * STRIDE_H];

    const int tid  = threadIdx.x;
    const int wid  = tid >> 5, lane = tid & 31;
    const int g    = lane >> 2, t = lane & 3;
    const int m0   = blockIdx.x * 128;
    const int n0   = blockIdx.y * 128;
    const int wm   = (wid & 3) * 32;
    const int wn   = (wid >> 2) * 64;

    float acc[2][8][4];
    #pragma unroll
    for (int i = 0; i < 2; ++i)
        #pragma unroll
        for (int j = 0; j < 8; ++j)
            #pragma unroll
            for (int q = 0; q < 4; ++q) acc[i][j][q] = 0.f;

    const uint32_t* A32hi = reinterpret_cast<const uint32_t*>(sAhi);
    const uint32_t* A32lo = reinterpret_cast<const uint32_t*>(sAlo);
    const uint32_t* B32hi = reinterpret_cast<const uint32_t*>(sBhi);
    const uint32_t* B32lo = reinterpret_cast<const uint32_t*>(sBlo);

    const int fr = tid >> 1;
    const int fh = tid & 1;
    const bool a_valid = (m0 + fr) < M;

    for (int c = 0; c < K_TOTAL / 32; ++c) {
        // ---- fill A (fp32 -> bf16 hi/lo) ----
        {
            const float* ap = A + (size_t)(m0 + fr) * K_TOTAL + c * 32 + fh * 16;
            #pragma unroll
            for (int q4 = 0; q4 < 2; ++q4) {
                float4 f0 = make_float4(0.f,0.f,0.f,0.f), f1 = f0;
                if (a_valid) {
                    f0 = *reinterpret_cast<const float4*>(ap + q4 * 8);
                    f1 = *reinterpret_cast<const float4*>(ap + q4 * 8 + 4);
                }
                uint4 Hv, Lv;
                Hv.x = pack_bf16(f0.x, f0.y); Hv.y = pack_bf16(f0.z, f0.w);
                Hv.z = pack_bf16(f1.x, f1.y); Hv.w = pack_bf16(f1.z, f1.w);
                float e0 = f0.x - __bfloat162float(__float2bfloat16_rn(f0.x));
                float e1 = f0.y - __bfloat162float(__float2bfloat16_rn(f0.y));
                float e2 = f0.z - __bfloat162float(__float2bfloat16_rn(f0.z));
                float e3 = f0.w - __bfloat162float(__float2bfloat16_rn(f0.w));
                float e4 = f1.x - __bfloat162float(__float2bfloat16_rn(f1.x));
                float e5 = f1.y - __bfloat162float(__float2bfloat16_rn(f1.y));
                float e6 = f1.z - __bfloat162float(__float2bfloat16_rn(f1.z));
                float e7 = f1.w - __bfloat162float(__float2bfloat16_rn(f1.w));
                Lv.x = pack_bf16(e0, e1); Lv.y = pack_bf16(e2, e3);
                Lv.z = pack_bf16(e4, e5); Lv.w = pack_bf16(e6, e7);
                int hw = fr * STRIDE_H + fh * 16 + q4 * 8;
                *reinterpret_cast<uint4*>(sAhi + hw) = Hv;
                *reinterpret_cast<uint4*>(sAlo + hw) = Lv;
            }
        }
        // ---- fill B ----
        {
            const size_t boff = (size_t)(n0 + fr) * K_TOTAL + c * 32 + fh * 16;
            const uint4* bh = reinterpret_cast<const uint4*>(Bhi + boff);
            const uint4* bl = reinterpret_cast<const uint4*>(Blo + boff);
            int hw = fr * STRIDE_H + fh * 16;
            *reinterpret_cast<uint4*>(sBhi + hw)     = bh[0];
            *reinterpret_cast<uint4*>(sBhi + hw + 8) = bh[1];
            *reinterpret_cast<uint4*>(sBlo + hw)     = bl[0];
            *reinterpret_cast<uint4*>(sBlo + hw + 8) = bl[1];
        }
        __syncthreads();

        // ---- compute ----
        #pragma unroll
        for (int ks = 0; ks < 2; ++ks) {
            const int kw = ks * 8;
            uint32_t ahi[2][4], alo[2][4];
            #pragma unroll
            for (int i = 0; i < 2; ++i) {
                int r0 = (wm + i * 16 + g) * (STRIDE_H / 2) + kw + t;
                ahi[i][0] = A32hi[r0];        ahi[i][1] = A32hi[r0 + 160];
                ahi[i][2] = A32hi[r0 + 4];    ahi[i][3] = A32hi[r0 + 164];
                alo[i][0] = A32lo[r0];        alo[i][1] = A32lo[r0 + 160];
                alo[i][2] = A32lo[r0 + 4];    alo[i][3] = A32lo[r0 + 164];
            }
            #pragma unroll
            for (int j = 0; j < 8; ++j) {
                int nb = (wn + j * 8 + g) * (STRIDE_H / 2) + kw + t;
                uint32_t bh0 = B32hi[nb], bh1 = B32hi[nb + 4];
                uint32_t bl0 = B32lo[nb], bl1 = B32lo[nb + 4];
                #pragma unroll
                for (int i = 0; i < 2; ++i) {
                    mma_bf16(acc[i][j], ahi[i], bh0, bh1);
                    mma_bf16(acc[i][j], ahi[i], bl0, bl1);
                    mma_bf16(acc[i][j], alo[i], bh0, bh1);
                }
            }
        }
        __syncthreads();
    }

    // ---- epilogue ----
    if (PROJ) {
        float s[4] = {0.f, 0.f, 0.f, 0.f};
        #pragma unroll
        for (int i = 0; i < 2; ++i)
            #pragma unroll
            for (int j = 0; j < 8; ++j) {
                int col = n0 + wn + j * 8 + t * 2;
                float w0 = __ldg(wout + col), w1 = __ldg(wout + col + 1);
                float b0 = BIAS ? __ldg(bias + col) : 0.f;
                float b1 = BIAS ? __ldg(bias + col + 1) : 0.f;
                float v0 = acc[i][j][0] + b0, v1 = acc[i][j][1] + b1;
                float v2 = acc[i][j][2] + b0, v3 = acc[i][j][3] + b1;
                if (SILU) {
                    v0 = v0 / (1.f + __expf(-v0)); v1 = v1 / (1.f + __expf(-v1));
                    v2 = v2 / (1.f + __expf(-v2)); v3 = v3 / (1.f + __expf(-v3));
                }
                s[i * 2 + 0] += v0 * w0 + v1 * w1;
                s[i * 2 + 1] += v2 * w0 + v3 * w1;
            }
        #pragma unroll
        for (int q = 0; q < 4; ++q) {
            s[q] += __shfl_xor_sync(0xffffffffu, s[q], 1);
            s[q] += __shfl_xor_sync(0xffffffffu, s[q], 2);
        }
        if (t == 0) {
            #pragma unroll
            for (int i = 0; i < 2; ++i) {
                int r0 = m0 + wm + i * 16 + g;
                if (r0 < M)
                    asm volatile("red.global.add.f32 [%0], %1;" :: "l"(Y + r0), "f"(s[i*2]) : "memory");
                if (r0 + 8 < M)
                    asm volatile("red.global.add.f32 [%0], %1;" :: "l"(Y + r0 + 8), "f"(s[i*2+1]) : "memory");
            }
        }
    } else {
        #pragma unroll
        for (int i = 0; i < 2; ++i) {
            int r0 = m0 + wm + i * 16 + g;
            #pragma unroll
            for (int j = 0; j < 8; ++j) {
                int col = n0 + wn + j * 8 + t * 2;
                float b0 = BIAS ? __ldg(bias + col) : 0.f;
                float b1 = BIAS ? __ldg(bias + col + 1) : 0.f;
                float v0 = acc[i][j][0] + b0, v1 = acc[i][j][1] + b1;
                float v2 = acc[i][j][2] + b0, v3 = acc[i][j][3] + b1;
                if (SILU) {
                    v0 = v0 / (1.f + __expf(-v0)); v1 = v1 / (1.f + __expf(-v1));
                    v2 = v2 / (1.f + __expf(-v2)); v3 = v3 / (1.f + __expf(-v3));
                }
                if (r0 < M)
                    *reinterpret_cast<float2*>(Y + (size_t)r0 * D_DIM + col) = make_float2(v0, v1);
                if (r0 + 8 < M)
                    *reinterpret_cast<float2*>(Y + (size_t)(r0 + 8) * D_DIM + col) = make_float2(v2, v3);
            }
        }
    }
}

// ---------------------------------------------------------------------------
// Launch
// Inputs: 0:x[E,128] 1:rbf[E,6] 2:i[E] 3:W_rbf[128,6] 4:W_up[256,128]
//         5:Ws[3,256,256] 6:bs[3,256] 7:W_out[1,256] (8:num_nodes)
// ---------------------------------------------------------------------------
extern "C" void kernel_launch(void* const* d_in, const int* in_sizes, int n_in,
                              void* d_out, int out_size) {
    const float* x     = (const float*)d_in[0];
    const float* rbf   = (const float*)d_in[1];
    const int*   idx   = (const int*)  d_in[2];
    const float* W_rbf = (const float*)d_in[3];
    const float* W_up  = (const float*)d_in[4];
    const float* Ws    = (const float*)d_in[5];
    const float* bs    = (const float*)d_in[6];
    const float* W_out = (const float*)d_in[7];
    float* out = (float*)d_out;

    const int E = in_sizes[2];
    const int M = out_size;

    float *agg, *y0, *y1;
    __nv_bfloat16 *whi, *wlo;
    cudaGetSymbolAddress((void**)&agg, g_agg);
    cudaGetSymbolAddress((void**)&y0,  g_y0);
    cudaGetSymbolAddress((void**)&y1,  g_y1);
    cudaGetSymbolAddress((void**)&whi, g_whi);
    cudaGetSymbolAddress((void**)&wlo, g_wlo);

    prep_w<<<224, 256>>>(W_up, Ws, whi, wlo);
    zero_kernel<<<1024, 256>>>((float4*)agg, M * H_DIM / 4);
    zero_kernel<<<128, 256>>>((float4*)out, M / 4);

    edge_kernel<<<444, 256>>>(x, rbf, idx, W_rbf, agg, E);

    const int tiles = (M + 127) / 128;
    dim3 grid(tiles, 2);
    const __nv_bfloat16* whi_l = whi + 256 * 128;
    const __nv_bfloat16* wlo_l = wlo + 256 * 128;

    // up-projection: y0 = agg @ W_up^T
    gemm_mma<128, false, false, false><<<grid, 256>>>(agg, whi, wlo, nullptr, nullptr, y0, M);
    // layer 0: y1 = silu(y0 @ W0^T + b0)
    gemm_mma<256, true, true, false><<<grid, 256>>>(y0, whi_l + 0*65536, wlo_l + 0*65536, bs + 0*D_DIM, nullptr, y1, M);
    // layer 1: y0 = silu(y1 @ W1^T + b1)
    gemm_mma<256, true, true, false><<<grid, 256>>>(y1, whi_l + 1*65536, wlo_l + 1*65536, bs + 1*D_DIM, nullptr, y0, M);
    // layer 2 + fused projection into out
    gemm_mma<256, true, true, true ><<<grid, 256>>>(y0, whi_l + 2*65536, wlo_l + 2*65536, bs + 2*D_DIM, W_out, out, M);
}